// round 3
// baseline (speedup 1.0000x reference)
#include <cuda_runtime.h>
#include <cstdint>

// Problem constants (fixed shapes per reference)
#define B_  2
#define H_  16
#define SQ_ 2048
#define SKV_ 3072
#define D_  64
#define NPT_ 1024

#define BM 64     // query rows per CTA
#define BN 64     // kv cols per tile
#define NTHREADS 256

__device__ __forceinline__ float ex2f(float x) {
    float y;
    asm("ex2.approx.ftz.f32 %0, %1;" : "=f"(y) : "f"(x));
    return y;
}

__global__ void __launch_bounds__(NTHREADS, 2)
fa_prefix_causal_kernel(const float* __restrict__ Q,
                        const float* __restrict__ K,
                        const float* __restrict__ V,
                        float* __restrict__ O)
{
    // 3 x 16KB = 49152 B static smem (fits the 48KB static limit exactly)
    __shared__ float Qs[BM * D_];     // Q tile, row-major, pre-scaled
    __shared__ float KsT[D_ * BN];    // K^T, xor-swizzled; reused as P after S GEMM
    __shared__ float Vs[BN * D_];     // V tile, row-major

    const int tid = threadIdx.x;
    const int tx = tid & 15;          // 16 column-groups
    const int ty = tid >> 4;          // 16 row-groups
    const int r0 = ty << 2;           // this thread's 4 rows
    const int c0 = tx << 2;           // this thread's 4 cols

    const int qb = blockIdx.x;        // 0..31
    const int bh = blockIdx.y;        // 0..31 (b*H+h)
    const int q0 = qb * BM;

    const float* q = Q + (size_t)bh * SQ_ * D_;
    const float* k = K + (size_t)bh * SKV_ * D_;
    const float* v = V + (size_t)bh * SKV_ * D_;
    float*       o = O + (size_t)bh * SQ_ * D_;

    // ---- load Q tile, fold in scale * log2(e) so softmax runs in exp2 domain
    const float qscale = 0.125f * 1.44269504088896340736f; // 1/sqrt(64) * log2(e)
    #pragma unroll
    for (int i = 0; i < 4; i++) {
        int e4  = tid + i * NTHREADS;         // 1024 float4s
        int row = e4 >> 4;
        int col = (e4 & 15) << 2;
        float4 t = *(const float4*)(q + (size_t)(q0 + row) * D_ + col);
        t.x *= qscale; t.y *= qscale; t.z *= qscale; t.w *= qscale;
        *(float4*)&Qs[row * D_ + col] = t;
    }

    float m[4], l[4], oacc[4][4];
    #pragma unroll
    for (int i = 0; i < 4; i++) {
        m[i] = -1e30f; l[i] = 0.f;
        #pragma unroll
        for (int j = 0; j < 4; j++) oacc[i][j] = 0.f;
    }

    // visible KV tiles: 0 .. qb+16 (mask collapses to kv <= q + 1024);
    // only the last tile needs masking, and it is exactly the diagonal c<=r.
    const int ntiles = qb + (NPT_ / BN) + 1;

    for (int t = 0; t < ntiles; t++) {
        __syncthreads();   // prior iteration done reading Ps(=KsT) and Vs

        // ---- load K tile transposed with (d&28) xor swizzle, V tile natural
        const float* kt = k + (size_t)t * BN * D_;
        const float* vt = v + (size_t)t * BN * D_;
        #pragma unroll
        for (int i = 0; i < 4; i++) {
            int e4 = tid + i * NTHREADS;
            int n  = e4 >> 4;                 // kv index in tile
            int d0 = (e4 & 15) << 2;          // head-dim base
            float4 kk4 = *(const float4*)(kt + n * D_ + d0);
            int sw = n ^ (d0 & 28);
            KsT[(d0 + 0) * BN + sw] = kk4.x;
            KsT[(d0 + 1) * BN + sw] = kk4.y;
            KsT[(d0 + 2) * BN + sw] = kk4.z;
            KsT[(d0 + 3) * BN + sw] = kk4.w;
            *(float4*)&Vs[n * D_ + d0] = *(const float4*)(vt + n * D_ + d0);
        }
        __syncthreads();

        // ---- S = (Q*scale) K^T : 4x4 register micro-tile, vectorized smem reads
        float s[4][4];
        #pragma unroll
        for (int i = 0; i < 4; i++)
            #pragma unroll
            for (int j = 0; j < 4; j++) s[i][j] = 0.f;

        #pragma unroll 4
        for (int kk4 = 0; kk4 < D_; kk4 += 4) {
            float A[4][4];
            #pragma unroll
            for (int i = 0; i < 4; i++) {
                float4 t4 = *(const float4*)&Qs[(r0 + i) * D_ + kk4];
                A[i][0] = t4.x; A[i][1] = t4.y; A[i][2] = t4.z; A[i][3] = t4.w;
            }
            #pragma unroll
            for (int u = 0; u < 4; u++) {
                int kk = kk4 + u;
                float4 b4 = *(const float4*)&KsT[kk * BN + (c0 ^ (kk & 28))];
                #pragma unroll
                for (int i = 0; i < 4; i++) {
                    s[i][0] = fmaf(A[i][u], b4.x, s[i][0]);
                    s[i][1] = fmaf(A[i][u], b4.y, s[i][1]);
                    s[i][2] = fmaf(A[i][u], b4.z, s[i][2]);
                    s[i][3] = fmaf(A[i][u], b4.w, s[i][3]);
                }
            }
        }

        // ---- diagonal mask, only on the last tile
        if (t == ntiles - 1) {
            #pragma unroll
            for (int i = 0; i < 4; i++)
                #pragma unroll
                for (int j = 0; j < 4; j++)
                    if (c0 + j > r0 + i) s[i][j] = -1e30f;
        }

        // ---- online softmax (exp2 domain); row group = 16 lanes (half-warp aligned)
        float corr[4];
        #pragma unroll
        for (int i = 0; i < 4; i++) {
            float mx = fmaxf(fmaxf(s[i][0], s[i][1]), fmaxf(s[i][2], s[i][3]));
            #pragma unroll
            for (int off = 8; off >= 1; off >>= 1)
                mx = fmaxf(mx, __shfl_xor_sync(0xffffffffu, mx, off));
            float mnew = fmaxf(m[i], mx);
            corr[i] = ex2f(m[i] - mnew);
            m[i] = mnew;
            float ps = 0.f;
            #pragma unroll
            for (int j = 0; j < 4; j++) {
                s[i][j] = ex2f(s[i][j] - mnew);
                ps += s[i][j];
            }
            #pragma unroll
            for (int off = 8; off >= 1; off >>= 1)
                ps += __shfl_xor_sync(0xffffffffu, ps, off);
            l[i] = l[i] * corr[i] + ps;
            #pragma unroll
            for (int j = 0; j < 4; j++) oacc[i][j] *= corr[i];
        }

        __syncthreads();             // all threads done reading KsT
        float* Ps = KsT;             // reuse dead K buffer for P
        #pragma unroll
        for (int i = 0; i < 4; i++)
            *(float4*)&Ps[(r0 + i) * BN + c0] =
                make_float4(s[i][0], s[i][1], s[i][2], s[i][3]);
        __syncthreads();

        // ---- O += P V : same micro-tile shape, all LDS.128
        #pragma unroll 4
        for (int kk4 = 0; kk4 < BN; kk4 += 4) {
            float P[4][4];
            #pragma unroll
            for (int i = 0; i < 4; i++) {
                float4 t4 = *(const float4*)&Ps[(r0 + i) * BN + kk4];
                P[i][0] = t4.x; P[i][1] = t4.y; P[i][2] = t4.z; P[i][3] = t4.w;
            }
            #pragma unroll
            for (int u = 0; u < 4; u++) {
                float4 v4 = *(const float4*)&Vs[(kk4 + u) * D_ + c0];
                #pragma unroll
                for (int i = 0; i < 4; i++) {
                    oacc[i][0] = fmaf(P[i][u], v4.x, oacc[i][0]);
                    oacc[i][1] = fmaf(P[i][u], v4.y, oacc[i][1]);
                    oacc[i][2] = fmaf(P[i][u], v4.z, oacc[i][2]);
                    oacc[i][3] = fmaf(P[i][u], v4.w, oacc[i][3]);
                }
            }
        }
    }

    // ---- epilogue: normalize and store
    #pragma unroll
    for (int i = 0; i < 4; i++) {
        float inv = 1.0f / l[i];
        float4 r;
        r.x = oacc[i][0] * inv;
        r.y = oacc[i][1] * inv;
        r.z = oacc[i][2] * inv;
        r.w = oacc[i][3] * inv;
        *(float4*)(o + (size_t)(q0 + r0 + i) * D_ + c0) = r;
    }
}

extern "C" void kernel_launch(void* const* d_in, const int* in_sizes, int n_in,
                              void* d_out, int out_size) {
    const float* q = (const float*)d_in[0];
    const float* k = (const float*)d_in[1];
    const float* v = (const float*)d_in[2];
    // d_in[3] = num_pt (fixed at 1024 per the problem spec; folded into tiling)
    float* out = (float*)d_out;

    dim3 grid(SQ_ / BM, B_ * H_);
    fa_prefix_causal_kernel<<<grid, NTHREADS>>>(q, k, v, out);
}

// round 4
// speedup vs baseline: 1.0159x; 1.0159x over previous
#include <cuda_runtime.h>
#include <cstdint>

// Problem constants (fixed shapes per reference)
#define B_  2
#define H_  16
#define SQ_ 2048
#define SKV_ 3072
#define D_  64
#define NPT_ 1024

#define BM 64     // query rows per CTA
#define BN 64     // kv cols per tile
#define NTHREADS 256

__device__ __forceinline__ float ex2f(float x) {
    float y;
    asm("ex2.approx.ftz.f32 %0, %1;" : "=f"(y) : "f"(x));
    return y;
}

__global__ void __launch_bounds__(NTHREADS, 2)
fa_prefix_causal_kernel(const float* __restrict__ Q,
                        const float* __restrict__ K,
                        const float* __restrict__ V,
                        float* __restrict__ O)
{
    // 3 x 16KB = 49152 B static smem (fits the 48KB static limit exactly)
    __shared__ float Qs[BM * D_];     // Q tile, row-major, pre-scaled
    __shared__ float KsT[D_ * BN];    // K^T, xor-swizzled; reused as P after S GEMM
    __shared__ float Vs[BN * D_];     // V tile, row-major

    const int tid = threadIdx.x;
    const int tx = tid & 15;          // 16 column-groups
    const int ty = tid >> 4;          // 16 row-groups
    const int r0 = ty << 2;           // this thread's 4 rows
    const int c0 = tx << 2;           // this thread's 4 cols

    const int qb = blockIdx.x;        // 0..31
    const int bh = blockIdx.y;        // 0..31 (b*H+h)
    const int q0 = qb * BM;

    const float* q = Q + (size_t)bh * SQ_ * D_;
    const float* k = K + (size_t)bh * SKV_ * D_;
    const float* v = V + (size_t)bh * SKV_ * D_;
    float*       o = O + (size_t)bh * SQ_ * D_;

    // ---- load Q tile, fold in scale * log2(e) so softmax runs in exp2 domain
    const float qscale = 0.125f * 1.44269504088896340736f; // 1/sqrt(64) * log2(e)
    #pragma unroll
    for (int i = 0; i < 4; i++) {
        int e4  = tid + i * NTHREADS;         // 1024 float4s
        int row = e4 >> 4;
        int col = (e4 & 15) << 2;
        float4 t = *(const float4*)(q + (size_t)(q0 + row) * D_ + col);
        t.x *= qscale; t.y *= qscale; t.z *= qscale; t.w *= qscale;
        *(float4*)&Qs[row * D_ + col] = t;
    }

    float m[4], l[4], oacc[4][4];
    #pragma unroll
    for (int i = 0; i < 4; i++) {
        m[i] = -1e30f; l[i] = 0.f;
        #pragma unroll
        for (int j = 0; j < 4; j++) oacc[i][j] = 0.f;
    }

    // visible KV tiles: 0 .. qb+16 (mask collapses to kv <= q + 1024);
    // only the last tile needs masking, and it is exactly the diagonal c<=r.
    const int ntiles = qb + (NPT_ / BN) + 1;

    for (int t = 0; t < ntiles; t++) {
        __syncthreads();   // prior iteration done reading Ps(=KsT) and Vs

        // ---- load K tile transposed with (d&28) xor swizzle, V tile natural
        const float* kt = k + (size_t)t * BN * D_;
        const float* vt = v + (size_t)t * BN * D_;
        #pragma unroll
        for (int i = 0; i < 4; i++) {
            int e4 = tid + i * NTHREADS;
            int n  = e4 >> 4;                 // kv index in tile
            int d0 = (e4 & 15) << 2;          // head-dim base
            float4 kk4 = *(const float4*)(kt + n * D_ + d0);
            int sw = n ^ (d0 & 28);
            KsT[(d0 + 0) * BN + sw] = kk4.x;
            KsT[(d0 + 1) * BN + sw] = kk4.y;
            KsT[(d0 + 2) * BN + sw] = kk4.z;
            KsT[(d0 + 3) * BN + sw] = kk4.w;
            *(float4*)&Vs[n * D_ + d0] = *(const float4*)(vt + n * D_ + d0);
        }
        __syncthreads();

        // ---- S = (Q*scale) K^T : 4x4 register micro-tile, vectorized smem reads
        float s[4][4];
        #pragma unroll
        for (int i = 0; i < 4; i++)
            #pragma unroll
            for (int j = 0; j < 4; j++) s[i][j] = 0.f;

        #pragma unroll 4
        for (int kk4 = 0; kk4 < D_; kk4 += 4) {
            float A[4][4];
            #pragma unroll
            for (int i = 0; i < 4; i++) {
                float4 t4 = *(const float4*)&Qs[(r0 + i) * D_ + kk4];
                A[i][0] = t4.x; A[i][1] = t4.y; A[i][2] = t4.z; A[i][3] = t4.w;
            }
            #pragma unroll
            for (int u = 0; u < 4; u++) {
                int kk = kk4 + u;
                float4 b4 = *(const float4*)&KsT[kk * BN + (c0 ^ (kk & 28))];
                #pragma unroll
                for (int i = 0; i < 4; i++) {
                    s[i][0] = fmaf(A[i][u], b4.x, s[i][0]);
                    s[i][1] = fmaf(A[i][u], b4.y, s[i][1]);
                    s[i][2] = fmaf(A[i][u], b4.z, s[i][2]);
                    s[i][3] = fmaf(A[i][u], b4.w, s[i][3]);
                }
            }
        }

        // ---- diagonal mask, only on the last tile
        if (t == ntiles - 1) {
            #pragma unroll
            for (int i = 0; i < 4; i++)
                #pragma unroll
                for (int j = 0; j < 4; j++)
                    if (c0 + j > r0 + i) s[i][j] = -1e30f;
        }

        // ---- online softmax (exp2 domain); row group = 16 lanes (half-warp aligned)
        float corr[4];
        #pragma unroll
        for (int i = 0; i < 4; i++) {
            float mx = fmaxf(fmaxf(s[i][0], s[i][1]), fmaxf(s[i][2], s[i][3]));
            #pragma unroll
            for (int off = 8; off >= 1; off >>= 1)
                mx = fmaxf(mx, __shfl_xor_sync(0xffffffffu, mx, off));
            float mnew = fmaxf(m[i], mx);
            corr[i] = ex2f(m[i] - mnew);
            m[i] = mnew;
            float ps = 0.f;
            #pragma unroll
            for (int j = 0; j < 4; j++) {
                s[i][j] = ex2f(s[i][j] - mnew);
                ps += s[i][j];
            }
            #pragma unroll
            for (int off = 8; off >= 1; off >>= 1)
                ps += __shfl_xor_sync(0xffffffffu, ps, off);
            l[i] = l[i] * corr[i] + ps;
            #pragma unroll
            for (int j = 0; j < 4; j++) oacc[i][j] *= corr[i];
        }

        __syncthreads();             // all threads done reading KsT
        float* Ps = KsT;             // reuse dead K buffer for P
        #pragma unroll
        for (int i = 0; i < 4; i++)
            *(float4*)&Ps[(r0 + i) * BN + c0] =
                make_float4(s[i][0], s[i][1], s[i][2], s[i][3]);
        __syncthreads();

        // ---- O += P V : same micro-tile shape, all LDS.128
        #pragma unroll 4
        for (int kk4 = 0; kk4 < BN; kk4 += 4) {
            float P[4][4];
            #pragma unroll
            for (int i = 0; i < 4; i++) {
                float4 t4 = *(const float4*)&Ps[(r0 + i) * BN + kk4];
                P[i][0] = t4.x; P[i][1] = t4.y; P[i][2] = t4.z; P[i][3] = t4.w;
            }
            #pragma unroll
            for (int u = 0; u < 4; u++) {
                float4 v4 = *(const float4*)&Vs[(kk4 + u) * D_ + c0];
                #pragma unroll
                for (int i = 0; i < 4; i++) {
                    oacc[i][0] = fmaf(P[i][u], v4.x, oacc[i][0]);
                    oacc[i][1] = fmaf(P[i][u], v4.y, oacc[i][1]);
                    oacc[i][2] = fmaf(P[i][u], v4.z, oacc[i][2]);
                    oacc[i][3] = fmaf(P[i][u], v4.w, oacc[i][3]);
                }
            }
        }
    }

    // ---- epilogue: normalize and store
    #pragma unroll
    for (int i = 0; i < 4; i++) {
        float inv = 1.0f / l[i];
        float4 r;
        r.x = oacc[i][0] * inv;
        r.y = oacc[i][1] * inv;
        r.z = oacc[i][2] * inv;
        r.w = oacc[i][3] * inv;
        *(float4*)(o + (size_t)(q0 + r0 + i) * D_ + c0) = r;
    }
}

extern "C" void kernel_launch(void* const* d_in, const int* in_sizes, int n_in,
                              void* d_out, int out_size) {
    const float* q = (const float*)d_in[0];
    const float* k = (const float*)d_in[1];
    const float* v = (const float*)d_in[2];
    // d_in[3] = num_pt (fixed at 1024 per the problem spec; folded into tiling)
    float* out = (float*)d_out;

    dim3 grid(SQ_ / BM, B_ * H_);
    fa_prefix_causal_kernel<<<grid, NTHREADS>>>(q, k, v, out);
}